// round 6
// baseline (speedup 1.0000x reference)
#include <cuda_runtime.h>
#include <cuda_fp16.h>
#include <cstdint>

#define N_USERS 100000
#define N_ITEMS 50000
#define N_NODES (N_USERS + N_ITEMS)
#define EMB 64
#define BATCH 4096
#define E_MAX 1500000

// ---- static scratch (no allocations allowed) ----
__device__ __half g_q0[(size_t)N_NODES * EMB];    // 19.2 MB  dinv*emb
__device__ __half g_q1[(size_t)N_NODES * EMB];    // 19.2 MB
__device__ __half g_q2[(size_t)N_NODES * EMB];    // 19.2 MB
__device__ int    g_deg   [N_NODES];              // zero-init at load; re-zeroed by k_fill
__device__ float  g_dinv  [N_NODES];
__device__ int    g_rs    [N_NODES + 1];
__device__ int    g_cursor[N_NODES];
__device__ int    g_col   [2 * E_MAX + 16];       // padded for int4 over-read
__device__ int    g_bsum  [256];

#define SCAN_T 1024
#define SCAN_BLOCKS ((N_NODES + SCAN_T - 1) / SCAN_T)   // 147

// ---------------------------------------------------------------------------
__global__ void k_hist(const int* __restrict__ eu, const int* __restrict__ ei,
                       int* __restrict__ deg, int E) {
    int i = blockIdx.x * blockDim.x + threadIdx.x;
    if (i >= E) return;
    atomicAdd(&deg[eu[i]], 1);
    atomicAdd(&deg[ei[i] + N_USERS], 1);
}

// Block-local exclusive scan of deg -> rs (pre-offset), block sums -> bsum,
// dinv = rsqrt(deg), and q0 = dinv*emb (fp16) all in one kernel.
__global__ void k_scan1(const int* __restrict__ deg, int* __restrict__ rs,
                        int* __restrict__ bsum, float* __restrict__ dinv,
                        const float4* __restrict__ emb, uint2* __restrict__ q0) {
    __shared__ int sh[SCAN_T];
    int gid = blockIdx.x * SCAN_T + threadIdx.x;
    int v = (gid < N_NODES) ? deg[gid] : 0;
    float d = (v > 0) ? rsqrtf((float)v) : 1.0f;
    if (gid < N_NODES) dinv[gid] = d;
    sh[threadIdx.x] = v;
    __syncthreads();
    for (int off = 1; off < SCAN_T; off <<= 1) {
        int t = (threadIdx.x >= off) ? sh[threadIdx.x - off] : 0;
        __syncthreads();
        sh[threadIdx.x] += t;
        __syncthreads();
    }
    if (gid < N_NODES) rs[gid] = sh[threadIdx.x] - v;   // exclusive (pre-offset)
    if (threadIdx.x == SCAN_T - 1) bsum[blockIdx.x] = sh[threadIdx.x];

    // fused q0 conversion for this node
    if (gid < N_NODES) {
        const float4* e = emb + (size_t)gid * (EMB / 4);
        uint2* q = q0 + (size_t)gid * (EMB / 4);
        #pragma unroll
        for (int k = 0; k < EMB / 4; ++k) {
            float4 x = e[k];
            __half2 a = __floats2half2_rn(x.x * d, x.y * d);
            __half2 b = __floats2half2_rn(x.z * d, x.w * d);
            uint2 o;
            o.x = *(unsigned*)&a;
            o.y = *(unsigned*)&b;
            q[k] = o;
        }
    }
}

// Merged scan2+scan3: every block scans the 147 block sums redundantly in
// shared, then applies its offset to rs and initializes cursor.
__global__ void k_scanB(int* __restrict__ rs, const int* __restrict__ bsum,
                        int* __restrict__ cursor, int E2) {
    __shared__ int sh[256];
    int t = threadIdx.x;
    int v = 0;
    if (t < 256) {
        v = (t < SCAN_BLOCKS) ? bsum[t] : 0;
        sh[t] = v;
    }
    __syncthreads();
    for (int off = 1; off < 256; off <<= 1) {
        int tmp = (t < 256 && t >= off) ? sh[t - off] : 0;
        __syncthreads();
        if (t < 256) sh[t] += tmp;
        __syncthreads();
    }
    if (t < 256) sh[t] -= v;   // exclusive
    __syncthreads();

    int offset = sh[blockIdx.x];
    int gid = blockIdx.x * SCAN_T + t;
    if (gid < N_NODES) {
        int r = rs[gid] + offset;
        rs[gid] = r;
        cursor[gid] = r;
    }
    if (gid == 0) rs[N_NODES] = E2;   // sentinel
}

// Fill CSR columns; also zero deg for the NEXT graph replay (deg is no longer
// read after k_scanB within a replay).
__global__ void k_fill(const int* __restrict__ eu, const int* __restrict__ ei,
                       int* __restrict__ cursor, int* __restrict__ col,
                       int* __restrict__ deg, int E) {
    int i = blockIdx.x * blockDim.x + threadIdx.x;
    if (i >= E) return;
    if (i < N_NODES) deg[i] = 0;
    int u  = eu[i];
    int it = ei[i] + N_USERS;
    col[atomicAdd(&cursor[u],  1)] = it;
    col[atomicAdd(&cursor[it], 1)] = u;
}

// ---------------------------------------------------------------------------
// Warp-cooperative fp16 row gather-sum (quarter-warp per edge, uint4 loads).
// On return every lane holds the full-row sum for its 8 columns.
__device__ __forceinline__ void row_sum_h(const __half* __restrict__ qin,
                                          const int* __restrict__ col,
                                          int beg, int end, int lane,
                                          float acc[8]) {
    int quarter = lane >> 3;
    int sub = lane & 7;
    #pragma unroll
    for (int k = 0; k < 8; ++k) acc[k] = 0.0f;

    for (int e0 = (beg & ~3); e0 < end; e0 += 16) {
        int base = e0 + 4 * quarter;
        int4 c4 = *(const int4*)(col + base);
        int cs[4] = {c4.x, c4.y, c4.z, c4.w};
        #pragma unroll
        for (int j = 0; j < 4; ++j) {
            int idx = base + j;
            if (idx >= beg && idx < end) {
                uint4 qv = *((const uint4*)(qin + (size_t)cs[j] * EMB) + sub);
                const __half2* hp = (const __half2*)&qv;
                float2 f0 = __half22float2(hp[0]);
                float2 f1 = __half22float2(hp[1]);
                float2 f2 = __half22float2(hp[2]);
                float2 f3 = __half22float2(hp[3]);
                acc[0] += f0.x; acc[1] += f0.y;
                acc[2] += f1.x; acc[3] += f1.y;
                acc[4] += f2.x; acc[5] += f2.y;
                acc[6] += f3.x; acc[7] += f3.y;
            }
        }
    }
    #pragma unroll
    for (int k = 0; k < 8; ++k) {
        acc[k] += __shfl_xor_sync(0xFFFFFFFFu, acc[k], 8);
        acc[k] += __shfl_xor_sync(0xFFFFFFFFu, acc[k], 16);
    }
}

// Pull layer: qout[n] = dinv[n]^2 * sum_{s in N(n)} qin[s]
__global__ void __launch_bounds__(256)
k_pull_h(const __half* __restrict__ qin, __half* __restrict__ qout,
         const int* __restrict__ rs, const int* __restrict__ col,
         const float* __restrict__ dinv) {
    int tid = blockIdx.x * blockDim.x + threadIdx.x;
    int n = tid >> 5;
    if (n >= N_NODES) return;
    int lane = tid & 31;

    int beg = rs[n];
    int end = rs[n + 1];

    float acc[8];
    row_sum_h(qin, col, beg, end, lane, acc);

    if (lane < 8) {
        float d = dinv[n];
        float s = d * d;
        __half2 h0 = __floats2half2_rn(acc[0] * s, acc[1] * s);
        __half2 h1 = __floats2half2_rn(acc[2] * s, acc[3] * s);
        __half2 h2 = __floats2half2_rn(acc[4] * s, acc[5] * s);
        __half2 h3 = __floats2half2_rn(acc[6] * s, acc[7] * s);
        uint4 o;
        o.x = *(unsigned*)&h0; o.y = *(unsigned*)&h1;
        o.z = *(unsigned*)&h2; o.w = *(unsigned*)&h3;
        *((uint4*)(qout + (size_t)n * EMB) + lane) = o;
    }
}

// ---------------------------------------------------------------------------
// Fused layer-3 + epilogue. One warp per (role, batch-row), n = node id:
//   rep3 = dinv[n] * sum q2[s]
//   final = 0.25 * ( emb[n] + sq*(q1[n]+q2[n]) + rep3 ),  sq = 1/dinv[n]
__global__ void __launch_bounds__(256)
k_final(float* __restrict__ out,
        const float* __restrict__ emb,
        const __half* __restrict__ q1,
        const __half* __restrict__ q2,
        const int* __restrict__ rs, const int* __restrict__ col,
        const float* __restrict__ dinv,
        const int* __restrict__ users, const int* __restrict__ pos,
        const int* __restrict__ neg) {
    int tid = blockIdx.x * blockDim.x + threadIdx.x;
    int w = tid >> 5;
    if (w >= 3 * BATCH) return;
    int lane = tid & 31;

    int role = w / BATCH;
    int b = w - role * BATCH;
    int n = (role == 0) ? users[b]
          : (role == 1) ? (N_USERS + pos[b])
                        : (N_USERS + neg[b]);

    int beg = rs[n];
    int end = rs[n + 1];

    float acc[8];
    row_sum_h(q2, col, beg, end, lane, acc);

    if (lane < 8) {
        float d = dinv[n];
        float sq = __fdividef(1.0f, d);   // sqrt(deg), or 1 when deg==0
        size_t ro = (size_t)n * EMB + lane * 8;

        float4 e0 = *(const float4*)(emb + ro);
        float4 e1 = *(const float4*)(emb + ro + 4);
        uint4 a1 = *((const uint4*)(q1 + (size_t)n * EMB) + lane);
        uint4 a2 = *((const uint4*)(q2 + (size_t)n * EMB) + lane);
        const __half2* h1 = (const __half2*)&a1;
        const __half2* h2 = (const __half2*)&a2;

        float r[8];
        #pragma unroll
        for (int k = 0; k < 4; ++k) {
            float2 f1 = __half22float2(h1[k]);
            float2 f2 = __half22float2(h2[k]);
            r[2*k]   = sq * (f1.x + f2.x) + d * acc[2*k];
            r[2*k+1] = sq * (f1.y + f2.y) + d * acc[2*k+1];
        }
        float4 o0, o1;
        o0.x = (e0.x + r[0]) * 0.25f; o0.y = (e0.y + r[1]) * 0.25f;
        o0.z = (e0.z + r[2]) * 0.25f; o0.w = (e0.w + r[3]) * 0.25f;
        o1.x = (e1.x + r[4]) * 0.25f; o1.y = (e1.y + r[5]) * 0.25f;
        o1.z = (e1.z + r[6]) * 0.25f; o1.w = (e1.w + r[7]) * 0.25f;

        size_t wo = (size_t)(role * BATCH + b) * EMB + lane * 8;
        *(float4*)(out + wo)     = o0;
        *(float4*)(out + wo + 4) = o1;
    }

    if (role == 0) {
        int p = N_USERS + pos[b];
        int g = N_USERS + neg[b];
        int c = lane * 2;
        float2 eu = *(const float2*)(emb + (size_t)n * EMB + c);
        float2 ep = *(const float2*)(emb + (size_t)p * EMB + c);
        float2 eg = *(const float2*)(emb + (size_t)g * EMB + c);
        float sum = eu.x * eu.x + eu.y * eu.y
                  + ep.x * ep.x + ep.y * ep.y
                  + eg.x * eg.x + eg.y * eg.y;
        #pragma unroll
        for (int off = 16; off > 0; off >>= 1)
            sum += __shfl_xor_sync(0xFFFFFFFFu, sum, off);
        if (lane == 0)
            out[(size_t)3 * BATCH * EMB + b] = sum;
    }
}

// ---------------------------------------------------------------------------
extern "C" void kernel_launch(void* const* d_in, const int* in_sizes, int n_in,
                              void* d_out, int out_size) {
    const float* emb   = (const float*)d_in[0];
    const int*   eu    = (const int*)  d_in[1];
    const int*   ei    = (const int*)  d_in[2];
    const int*   users = (const int*)  d_in[3];
    const int*   pos   = (const int*)  d_in[4];
    const int*   neg   = (const int*)  d_in[5];
    float* out = (float*)d_out;
    const int E = in_sizes[1];

    __half *q0, *q1, *q2;
    float *dinv;
    int *deg, *rs, *cursor, *col, *bsum;
    cudaGetSymbolAddress((void**)&q0,     g_q0);
    cudaGetSymbolAddress((void**)&q1,     g_q1);
    cudaGetSymbolAddress((void**)&q2,     g_q2);
    cudaGetSymbolAddress((void**)&dinv,   g_dinv);
    cudaGetSymbolAddress((void**)&deg,    g_deg);
    cudaGetSymbolAddress((void**)&rs,     g_rs);
    cudaGetSymbolAddress((void**)&cursor, g_cursor);
    cudaGetSymbolAddress((void**)&col,    g_col);
    cudaGetSymbolAddress((void**)&bsum,   g_bsum);

    const int TB = 256;

    // ---- CSR build (deg zeroed by previous replay's k_fill / load-time init) ----
    k_hist<<<(E + TB - 1) / TB, TB>>>(eu, ei, deg, E);
    k_scan1<<<SCAN_BLOCKS, SCAN_T>>>(deg, rs, bsum, dinv, (const float4*)emb,
                                     (uint2*)q0);
    k_scanB<<<SCAN_BLOCKS, SCAN_T>>>(rs, bsum, cursor, 2 * E);
    k_fill<<<(E + TB - 1) / TB, TB>>>(eu, ei, cursor, col, deg, E);

    // ---- layers 1 & 2 ----
    const int pullBlocks = (N_NODES * 32 + TB - 1) / TB;
    k_pull_h<<<pullBlocks, TB>>>(q0, q1, rs, col, dinv);
    k_pull_h<<<pullBlocks, TB>>>(q1, q2, rs, col, dinv);

    // ---- fused layer 3 + epilogue ----
    const int finalBlocks = (3 * BATCH * 32 + TB - 1) / TB;
    k_final<<<finalBlocks, TB>>>(out, emb, q1, q2, rs, col, dinv,
                                 users, pos, neg);
}